// round 3
// baseline (speedup 1.0000x reference)
#include <cuda_runtime.h>
#include <cuda_bf16.h>
#include <math.h>

#define NN   16384
#define BB   256
#define NPG  64
#define DEG  8
#define EE   (NN*DEG)
#define HH   256
#define FN   133
#define FE   14
#define NPB  4    // nodes per block in fused aggregate kernels

// ---------------- scratch ----------------------------------------------------
__device__ float g_in  [NN*HH];
__device__ float g_hn  [NN*HH];
__device__ float g_tmp [NN*HH];
__device__ float g_cat [NN*3*HH];
__device__ float g_hnl [NN*HH];
__device__ float g_msg [NN*HH];
__device__ float g_xgf [NN*3*HH];
__device__ float g_xgb [NN*3*HH];
__device__ float g_hf0 [BB*HH];
__device__ float g_hf1 [BB*HH];
__device__ float g_hb0 [BB*HH];
__device__ float g_hb1 [BB*HH];
__device__ float g_accf[BB*HH];
__device__ float g_accb[BB*HH];

__device__ __forceinline__ float sigmoidf_(float x){ return 1.0f/(1.0f+expf(-x)); }

// ---------------- fp32 GEMM, 128x128x16 tiles, float4 inner LDS --------------
// C = op(A @ W + bias). blockIdx.z selects (W0,b0,C0) or (W1,b1,C1).
// M multiple of 128, N multiple of 128 (no store guards). K guarded.
template<bool RELU>
__global__ __launch_bounds__(256) void sgemm128(
    int M, int N, int K,
    const float* __restrict__ A,
    const float* __restrict__ W0, const float* __restrict__ b0, float* __restrict__ C0,
    const float* __restrict__ W1, const float* __restrict__ b1, float* __restrict__ C1)
{
    const float* W    = blockIdx.z ? W1 : W0;
    const float* bias = blockIdx.z ? b1 : b0;
    float*       C    = blockIdx.z ? C1 : C0;

    __shared__ float As[16][132];   // [k][m], row stride 132 floats (16B aligned)
    __shared__ float Ws[16][128];   // [k][n]
    const int tid = threadIdx.x;
    const int tx = tid & 15, ty = tid >> 4;
    const int row0 = blockIdx.y*128, col0 = blockIdx.x*128;

    float acc[8][8];
    #pragma unroll
    for (int i=0;i<8;i++)
        #pragma unroll
        for (int j=0;j<8;j++) acc[i][j]=0.f;

    for (int k0 = 0; k0 < K; k0 += 16){
        #pragma unroll 4
        for (int idx = tid; idx < 2048; idx += 256){
            int kk = idx & 15, m = idx >> 4;
            int gk = k0 + kk;
            As[kk][m] = (gk < K) ? A[(size_t)(row0+m)*K + gk] : 0.f;
        }
        #pragma unroll 4
        for (int idx = tid; idx < 2048; idx += 256){
            int n = idx & 127, kk = idx >> 7;
            int gk = k0 + kk;
            Ws[kk][n] = (gk < K) ? W[(size_t)gk*N + col0 + n] : 0.f;
        }
        __syncthreads();
        #pragma unroll
        for (int k = 0; k < 16; k++){
            float4 a0 = *(const float4*)&As[k][ty*8];
            float4 a1 = *(const float4*)&As[k][ty*8+4];
            float4 w0 = *(const float4*)&Ws[k][tx*8];
            float4 w1 = *(const float4*)&Ws[k][tx*8+4];
            float av[8] = {a0.x,a0.y,a0.z,a0.w,a1.x,a1.y,a1.z,a1.w};
            float bv[8] = {w0.x,w0.y,w0.z,w0.w,w1.x,w1.y,w1.z,w1.w};
            #pragma unroll
            for (int i=0;i<8;i++)
                #pragma unroll
                for (int j=0;j<8;j++)
                    acc[i][j] = fmaf(av[i], bv[j], acc[i][j]);
        }
        __syncthreads();
    }

    float bl[8];
    #pragma unroll
    for (int j=0;j<8;j++) bl[j] = bias[col0 + tx*8 + j];

    #pragma unroll
    for (int i=0;i<8;i++){
        size_t gr = (size_t)(row0 + ty*8 + i);
        float v[8];
        #pragma unroll
        for (int j=0;j<8;j++){
            v[j] = acc[i][j] + bl[j];
            if (RELU) v[j] = fmaxf(v[j], 0.f);
        }
        *(float4*)&C[gr*N + col0 + tx*8]     = make_float4(v[0],v[1],v[2],v[3]);
        *(float4*)&C[gr*N + col0 + tx*8 + 4] = make_float4(v[4],v[5],v[6],v[7]);
    }
}

// ---------- fused aggregate: on-the-fly i_e, optional tmp gather -------------
// HAS_TMP=0: h_e = i_e;  HAS_TMP=1: h_e = relu(i_e + tmp[src])
// hn_out = hn_in + segsum(h_e)*segmax(h_e)
template<bool HAS_TMP>
__global__ __launch_bounds__(256) void agg_k(
    const float* __restrict__ edge_x, const float* __restrict__ We,
    const float* __restrict__ be,     const float* __restrict__ tmp,
    const int* __restrict__ src,
    const float* __restrict__ hn_in,  float* __restrict__ hn_out)
{
    __shared__ float WeS[FE*HH];
    __shared__ float exs[NPB*DEG*FE];
    __shared__ int   srcS[NPB*DEG];
    const int tid = threadIdx.x;
    const int node0 = blockIdx.x * NPB;

    #pragma unroll
    for (int i = tid; i < FE*HH; i += 256) WeS[i] = We[i];
    for (int i = tid; i < NPB*DEG*FE; i += 256) exs[i] = edge_x[(size_t)node0*DEG*FE + i];
    if (tid < NPB*DEG) srcS[tid] = src[node0*DEG + tid];
    __syncthreads();

    const int j = tid;
    const float bej = be[j];
    #pragma unroll
    for (int nl = 0; nl < NPB; nl++){
        float tv[DEG];
        if (HAS_TMP){
            #pragma unroll
            for (int d=0; d<DEG; d++)
                tv[d] = tmp[(size_t)srcS[nl*DEG+d]*HH + j];
        }
        float s = 0.f, m = -INFINITY;
        #pragma unroll
        for (int d=0; d<DEG; d++){
            float v = bej;
            #pragma unroll
            for (int k=0; k<FE; k++)
                v = fmaf(exs[nl*DEG*FE + d*FE + k], WeS[k*HH + j], v);
            v = fmaxf(v, 0.f);
            if (HAS_TMP) v = fmaxf(v + tv[d], 0.f);
            s += v; m = fmaxf(m, v);
        }
        size_t r = (size_t)(node0+nl)*HH + j;
        hn_out[r] = hn_in[r] + s*m;
    }
}

// ---------- fused final aggregate + concat(m_final, h_n, i_n) ----------------
__global__ __launch_bounds__(256) void cat_k(
    const float* __restrict__ edge_x, const float* __restrict__ We,
    const float* __restrict__ be,     const float* __restrict__ tmp,
    const int* __restrict__ src,
    const float* __restrict__ hn,     const float* __restrict__ in_,
    float* __restrict__ cat)
{
    __shared__ float WeS[FE*HH];
    __shared__ float exs[NPB*DEG*FE];
    __shared__ int   srcS[NPB*DEG];
    const int tid = threadIdx.x;
    const int node0 = blockIdx.x * NPB;

    #pragma unroll
    for (int i = tid; i < FE*HH; i += 256) WeS[i] = We[i];
    for (int i = tid; i < NPB*DEG*FE; i += 256) exs[i] = edge_x[(size_t)node0*DEG*FE + i];
    if (tid < NPB*DEG) srcS[tid] = src[node0*DEG + tid];
    __syncthreads();

    const int j = tid;
    const float bej = be[j];
    #pragma unroll
    for (int nl = 0; nl < NPB; nl++){
        float tv[DEG];
        #pragma unroll
        for (int d=0; d<DEG; d++)
            tv[d] = tmp[(size_t)srcS[nl*DEG+d]*HH + j];
        float s = 0.f, m = -INFINITY;
        #pragma unroll
        for (int d=0; d<DEG; d++){
            float v = bej;
            #pragma unroll
            for (int k=0; k<FE; k++)
                v = fmaf(exs[nl*DEG*FE + d*FE + k], WeS[k*HH + j], v);
            v = fmaxf(v, 0.f);
            v = fmaxf(v + tv[d], 0.f);
            s += v; m = fmaxf(m, v);
        }
        int node = node0 + nl;
        size_t r = (size_t)node*3*HH;
        cat[r + j]        = s*m;
        cat[r + HH + j]   = hn[(size_t)node*HH + j];
        cat[r + 2*HH + j] = in_[(size_t)node*HH + j];
    }
}

// ---------- msg = relu(h_n + gbias) ------------------------------------------
__global__ void msg_k(const float* __restrict__ hnl, const float* __restrict__ gbias,
                      float* __restrict__ msg)
{
    int i = blockIdx.x, j = threadIdx.x;
    msg[(size_t)i*HH + j] = fmaxf(hnl[(size_t)i*HH + j] + gbias[j], 0.f);
}

// ---------- h0 = per-graph max; zero accumulators ----------------------------
__global__ void init_h0_k(const float* __restrict__ hnl,
                          float* __restrict__ hf, float* __restrict__ hb,
                          float* __restrict__ accf, float* __restrict__ accb)
{
    int b = blockIdx.x, j = threadIdx.x;
    float m = -INFINITY;
    #pragma unroll 8
    for (int t=0; t<NPG; t++)
        m = fmaxf(m, hnl[((size_t)b*NPG + t)*HH + j]);
    hf[b*HH+j] = m; hb[b*HH+j] = m;
    accf[b*HH+j] = 0.f; accb[b*HH+j] = 0.f;
}

// ---------- fused GRU step: gh GEMM + gates + h update + mean accumulate -----
// grid (8 j-tiles, 8 graph-tiles, 2 dirs), 256 threads.
// Block: 32 graphs x 32 hidden x 3 gates; K=256. Double-buffered h.
__global__ __launch_bounds__(256) void gru_step_k(
    const float* __restrict__ xgf, const float* __restrict__ xgb,
    const float* __restrict__ Whf, const float* __restrict__ Whb,
    const float* __restrict__ bhf, const float* __restrict__ bhb,
    const float* __restrict__ hf_in, const float* __restrict__ hb_in,
    float* __restrict__ hf_out, float* __restrict__ hb_out,
    float* __restrict__ accf, float* __restrict__ accb, int step)
{
    const int dir = blockIdx.z;
    const float* xg  = dir ? xgb : xgf;
    const float* Wh  = dir ? Whb : Whf;
    const float* bh  = dir ? bhb : bhf;
    const float* hin = dir ? hb_in : hf_in;
    float* hout = dir ? hb_out : hf_out;
    float* acc  = dir ? accb : accf;
    const int t = dir ? (NPG-1-step) : step;

    const int g0 = blockIdx.y*32, j0 = blockIdx.x*32;
    __shared__ float Hs[32][34];   // [k][g], even stride for float2
    __shared__ float Ws[32][98];   // [k][gate*32+jj]
    const int tid = threadIdx.x, tx = tid & 15, ty = tid >> 4;

    float a[2][6];
    #pragma unroll
    for (int i=0;i<2;i++)
        #pragma unroll
        for (int q=0;q<6;q++) a[i][q]=0.f;

    for (int k0 = 0; k0 < HH; k0 += 32){
        #pragma unroll
        for (int idx = tid; idx < 32*32; idx += 256){
            int kk = idx & 31, g = idx >> 5;
            Hs[kk][g] = hin[(size_t)(g0+g)*HH + k0 + kk];
        }
        #pragma unroll
        for (int idx = tid; idx < 32*96; idx += 256){
            int col = idx % 96, kk = idx / 96;
            int gate = col >> 5, jj = col & 31;
            Ws[kk][col] = Wh[(size_t)(k0+kk)*(3*HH) + gate*HH + j0 + jj];
        }
        __syncthreads();
        #pragma unroll
        for (int k=0;k<32;k++){
            float2 hv = *(const float2*)&Hs[k][ty*2];
            float2 b0 = *(const float2*)&Ws[k][ 0 + tx*2];
            float2 b1 = *(const float2*)&Ws[k][32 + tx*2];
            float2 b2 = *(const float2*)&Ws[k][64 + tx*2];
            a[0][0]=fmaf(hv.x,b0.x,a[0][0]); a[0][1]=fmaf(hv.x,b0.y,a[0][1]);
            a[0][2]=fmaf(hv.x,b1.x,a[0][2]); a[0][3]=fmaf(hv.x,b1.y,a[0][3]);
            a[0][4]=fmaf(hv.x,b2.x,a[0][4]); a[0][5]=fmaf(hv.x,b2.y,a[0][5]);
            a[1][0]=fmaf(hv.y,b0.x,a[1][0]); a[1][1]=fmaf(hv.y,b0.y,a[1][1]);
            a[1][2]=fmaf(hv.y,b1.x,a[1][2]); a[1][3]=fmaf(hv.y,b1.y,a[1][3]);
            a[1][4]=fmaf(hv.y,b2.x,a[1][4]); a[1][5]=fmaf(hv.y,b2.y,a[1][5]);
        }
        __syncthreads();
    }

    #pragma unroll
    for (int gm=0; gm<2; gm++){
        const int g = g0 + ty*2 + gm;
        const float* x = xg + ((size_t)g*NPG + t)*(3*HH);
        #pragma unroll
        for (int jj=0; jj<2; jj++){
            const int j = j0 + tx*2 + jj;
            float r = sigmoidf_(x[j]        + a[gm][0+jj] + bh[j]);
            float z = sigmoidf_(x[HH + j]   + a[gm][2+jj] + bh[HH + j]);
            float n = tanhf    (x[2*HH + j] + r*(a[gm][4+jj] + bh[2*HH + j]));
            float hold = hin[(size_t)g*HH + j];
            float hn = (1.0f - z)*n + z*hold;
            hout[(size_t)g*HH + j] = hn;
            acc[(size_t)g*HH + j] += hn;
        }
    }
}

// ---------- readout: out = relu(g@W1+b1)@W2 + b2 -----------------------------
__global__ void readout_k(const float* __restrict__ accf, const float* __restrict__ accb,
                          const float* __restrict__ W1, const float* __restrict__ b1,
                          const float* __restrict__ W2, const float* __restrict__ b2,
                          float* __restrict__ out)
{
    int b = blockIdx.x, j = threadIdx.x;
    __shared__ float gsh[2*HH];
    __shared__ float red[HH];
    gsh[j]      = accf[b*HH + j] * (1.0f/NPG);
    gsh[HH + j] = accb[b*HH + j] * (1.0f/NPG);
    __syncthreads();
    float y = b1[j];
    #pragma unroll 8
    for (int k=0; k<2*HH; k++)
        y = fmaf(gsh[k], W1[k*HH + j], y);
    y = fmaxf(y, 0.f);
    red[j] = y * W2[j];
    __syncthreads();
    for (int s=128; s>0; s>>=1){
        if (j < s) red[j] += red[j+s];
        __syncthreads();
    }
    if (j == 0) out[b] = red[0] + b2[0];
}

// =============================================================================
extern "C" void kernel_launch(void* const* d_in, const int* in_sizes, int n_in,
                              void* d_out, int out_size)
{
    const float* node_x = (const float*)d_in[0];
    const float* edge_x = (const float*)d_in[1];
    const int*   src    = (const int*)  d_in[2];
    const float* Wn  = (const float*)d_in[4];  const float* bn  = (const float*)d_in[5];
    const float* We  = (const float*)d_in[6];  const float* be  = (const float*)d_in[7];
    const float* Wm0 = (const float*)d_in[8];  const float* bm0 = (const float*)d_in[9];
    const float* Wm1 = (const float*)d_in[10]; const float* bm1 = (const float*)d_in[11];
    const float* Wlr = (const float*)d_in[12]; const float* blr = (const float*)d_in[13];
    const float* gbias = (const float*)d_in[14];
    const float* Wif = (const float*)d_in[15]; const float* Whf = (const float*)d_in[16];
    const float* bif = (const float*)d_in[17]; const float* bhf = (const float*)d_in[18];
    const float* Wib = (const float*)d_in[19]; const float* Whb = (const float*)d_in[20];
    const float* bib = (const float*)d_in[21]; const float* bhb = (const float*)d_in[22];
    const float* W1  = (const float*)d_in[23]; const float* b1  = (const float*)d_in[24];
    const float* W2  = (const float*)d_in[25]; const float* b2  = (const float*)d_in[26];
    float* out = (float*)d_out;

    float *p_in,*p_hn,*p_tmp,*p_cat,*p_hnl,*p_msg,*p_xgf,*p_xgb;
    float *p_hf0,*p_hf1,*p_hb0,*p_hb1,*p_accf,*p_accb;
    cudaGetSymbolAddress((void**)&p_in,  g_in);
    cudaGetSymbolAddress((void**)&p_hn,  g_hn);
    cudaGetSymbolAddress((void**)&p_tmp, g_tmp);
    cudaGetSymbolAddress((void**)&p_cat, g_cat);
    cudaGetSymbolAddress((void**)&p_hnl, g_hnl);
    cudaGetSymbolAddress((void**)&p_msg, g_msg);
    cudaGetSymbolAddress((void**)&p_xgf, g_xgf);
    cudaGetSymbolAddress((void**)&p_xgb, g_xgb);
    cudaGetSymbolAddress((void**)&p_hf0, g_hf0);
    cudaGetSymbolAddress((void**)&p_hf1, g_hf1);
    cudaGetSymbolAddress((void**)&p_hb0, g_hb0);
    cudaGetSymbolAddress((void**)&p_hb1, g_hb1);
    cudaGetSymbolAddress((void**)&p_accf, g_accf);
    cudaGetSymbolAddress((void**)&p_accb, g_accb);

    // 1) node embedding: i_n = relu(node_x @ Wn + bn)
    sgemm128<true><<<dim3(2,128,1), 256>>>(NN, HH, FN, node_x, Wn, bn, p_in, Wn, bn, p_in);

    // 2) round 1: h_n = i_n + segsum(i_e)*segmax(i_e)   (i_e computed on the fly)
    agg_k<false><<<NN/NPB, 256>>>(edge_x, We, be, nullptr, src, p_in, p_hn);
    sgemm128<false><<<dim3(2,128,1), 256>>>(NN, HH, HH, p_hn, Wm0, bm0, p_tmp, Wm0, bm0, p_tmp);

    // 3) round 2: h_e = relu(i_e + tmp[src]); h_n += segsum*segmax
    agg_k<true><<<NN/NPB, 256>>>(edge_x, We, be, p_tmp, src, p_hn, p_hn);
    sgemm128<false><<<dim3(2,128,1), 256>>>(NN, HH, HH, p_hn, Wm1, bm1, p_tmp, Wm1, bm1, p_tmp);

    // 4) final aggregate + concat + Wlr
    cat_k<<<NN/NPB, 256>>>(edge_x, We, be, p_tmp, src, p_hn, p_in, p_cat);
    sgemm128<false><<<dim3(2,128,1), 256>>>(NN, HH, 3*HH, p_cat, Wlr, blr, p_hnl, Wlr, blr, p_hnl);

    // 5) GRU setup
    msg_k<<<NN, HH>>>(p_hnl, gbias, p_msg);
    init_h0_k<<<BB, HH>>>(p_hnl, p_hf0, p_hb0, p_accf, p_accb);
    sgemm128<false><<<dim3(6,128,2), 256>>>(NN, 3*HH, HH, p_msg,
                                            Wif, bif, p_xgf, Wib, bib, p_xgb);

    // 6) GRU scan: 64 fused steps, double-buffered h
    for (int step = 0; step < NPG; step++){
        float* hf_in  = (step & 1) ? p_hf1 : p_hf0;
        float* hf_out = (step & 1) ? p_hf0 : p_hf1;
        float* hb_in  = (step & 1) ? p_hb1 : p_hb0;
        float* hb_out = (step & 1) ? p_hb0 : p_hb1;
        gru_step_k<<<dim3(8,8,2), 256>>>(p_xgf, p_xgb, Whf, Whb, bhf, bhb,
                                         hf_in, hb_in, hf_out, hb_out,
                                         p_accf, p_accb, step);
    }

    // 7) readout
    readout_k<<<BB, HH>>>(p_accf, p_accb, W1, b1, W2, b2, out);
}

// round 6
// speedup vs baseline: 1.1727x; 1.1727x over previous
#include <cuda_runtime.h>
#include <cuda_bf16.h>
#include <math.h>
#include <stdint.h>

#define NN   16384
#define BB   256
#define NPG  64
#define DEG  8
#define EE   (NN*DEG)
#define HH   256
#define FN   133
#define FE   14
#define NPB  4

// ---------------- scratch ----------------------------------------------------
__device__ float g_in  [NN*HH];
__device__ float g_hn  [NN*HH];
__device__ float g_tmp [NN*HH];
__device__ float g_cat [NN*3*HH];
__device__ float g_hnl [NN*HH];
__device__ float g_msg [NN*HH];
__device__ float g_xgf [NN*3*HH];
__device__ float g_xgb [NN*3*HH];
__device__ float g_hf0 [BB*HH];
__device__ float g_hf1 [BB*HH];
__device__ float g_hb0 [BB*HH];
__device__ float g_hb1 [BB*HH];
__device__ float g_accf[BB*HH];
__device__ float g_accb[BB*HH];
// transposed (N-major, K-padded) weights
__device__ float g_WnT [HH*160];
__device__ float g_Wm0T[HH*HH];
__device__ float g_Wm1T[HH*HH];
__device__ float g_WlrT[HH*3*HH];
__device__ float g_WifT[3*HH*HH];
__device__ float g_WibT[3*HH*HH];

__device__ __forceinline__ float sigmoidf_(float x){ return 1.0f/(1.0f+expf(-x)); }

// hi = round-to-nearest tf32(a); lo = a - hi (exact)
__device__ __forceinline__ void split_tf32(float a, float& hi, float& lo){
    uint32_t u;
    asm("cvt.rna.tf32.f32 %0, %1;" : "=r"(u) : "f"(a));
    hi = __uint_as_float(u);
    lo = a - hi;
}

#define MMA_TF32(c0,c1,c2,c3,a0,a1,a2,a3,b0,b1) \
  asm volatile("mma.sync.aligned.m16n8k8.row.col.f32.tf32.tf32.f32 " \
    "{%0,%1,%2,%3}, {%4,%5,%6,%7}, {%8,%9}, {%0,%1,%2,%3};" \
    : "+f"(c0),"+f"(c1),"+f"(c2),"+f"(c3) \
    : "r"(a0),"r"(a1),"r"(a2),"r"(a3),"r"(b0),"r"(b1))

// ---------------- weight transpose + K-pad prep ------------------------------
__global__ void prep_w(const float* __restrict__ W, float* __restrict__ Wt,
                       int K, int N, int Kpad)
{
    int idx = blockIdx.x*256 + threadIdx.x;
    if (idx >= N*Kpad) return;
    int n = idx / Kpad, k = idx - n*Kpad;
    Wt[idx] = (k < K) ? W[(size_t)k*N + n] : 0.f;
}

// ---------------- mma.sync tf32 GEMM (3xTF32 split) --------------------------
// C[M,N] = op(A[M,Ktrue] @ Wt^T + bias), Wt is [N][Kpad], Kpad % 32 == 0.
// grid(N/128, M/128), 256 threads = 8 warps (2 row x 4 col); warp tile 64x32.
#define GE_SMEM (4*128*36*4)
template<bool RELU>
__global__ __launch_bounds__(256) void mma_gemm(
    int M, int N, int Ktrue, int Kpad,
    const float* __restrict__ A, const float* __restrict__ Wt,
    const float* __restrict__ bias, float* __restrict__ C)
{
    extern __shared__ float sm[];
    float* Ah = sm;
    float* Al = Ah + 128*36;
    float* Bh = Al + 128*36;
    float* Bl = Bh + 128*36;
    const int tid = threadIdx.x, lane = tid & 31, wid = tid >> 5;
    const int wm = wid >> 2, wn = wid & 3;
    const int row0 = blockIdx.y*128, n0 = blockIdx.x*128;

    float c[4][4][4];
    #pragma unroll
    for (int mt=0; mt<4; mt++)
        #pragma unroll
        for (int nt=0; nt<4; nt++)
            #pragma unroll
            for (int q=0; q<4; q++) c[mt][nt][q] = 0.f;

    for (int k0 = 0; k0 < Kpad; k0 += 32){
        if ((Ktrue & 3) == 0){
            #pragma unroll
            for (int it=0; it<4; it++){
                int idx = it*256 + tid;
                int r = idx >> 3, cc = (idx & 7)*4;
                int gk = k0 + cc;
                float4 v = (gk < Ktrue) ? *(const float4*)&A[(size_t)(row0+r)*Ktrue + gk]
                                        : make_float4(0.f,0.f,0.f,0.f);
                float4 h4, l4;
                split_tf32(v.x,h4.x,l4.x); split_tf32(v.y,h4.y,l4.y);
                split_tf32(v.z,h4.z,l4.z); split_tf32(v.w,h4.w,l4.w);
                *(float4*)&Ah[r*36 + cc] = h4;
                *(float4*)&Al[r*36 + cc] = l4;
            }
        } else {
            #pragma unroll
            for (int it=0; it<16; it++){
                int idx = it*256 + tid;
                int r = idx >> 5, cc = idx & 31;
                int gk = k0 + cc;
                float v = (gk < Ktrue) ? A[(size_t)(row0+r)*Ktrue + gk] : 0.f;
                float h, l; split_tf32(v, h, l);
                Ah[r*36 + cc] = h; Al[r*36 + cc] = l;
            }
        }
        #pragma unroll
        for (int it=0; it<4; it++){
            int idx = it*256 + tid;
            int r = idx >> 3, cc = (idx & 7)*4;
            float4 v = *(const float4*)&Wt[(size_t)(n0+r)*Kpad + k0 + cc];
            float4 h4, l4;
            split_tf32(v.x,h4.x,l4.x); split_tf32(v.y,h4.y,l4.y);
            split_tf32(v.z,h4.z,l4.z); split_tf32(v.w,h4.w,l4.w);
            *(float4*)&Bh[r*36 + cc] = h4;
            *(float4*)&Bl[r*36 + cc] = l4;
        }
        __syncthreads();

        #pragma unroll
        for (int kk=0; kk<32; kk+=8){
            uint32_t ah[4][4], al[4][4], bh[4][2], bl[4][2];
            const int cb = kk + (lane & 3);
            #pragma unroll
            for (int mt=0; mt<4; mt++){
                int r = wm*64 + mt*16 + (lane>>2);
                ah[mt][0] = __float_as_uint(Ah[r*36 + cb]);
                ah[mt][1] = __float_as_uint(Ah[(r+8)*36 + cb]);
                ah[mt][2] = __float_as_uint(Ah[r*36 + cb + 4]);
                ah[mt][3] = __float_as_uint(Ah[(r+8)*36 + cb + 4]);
                al[mt][0] = __float_as_uint(Al[r*36 + cb]);
                al[mt][1] = __float_as_uint(Al[(r+8)*36 + cb]);
                al[mt][2] = __float_as_uint(Al[r*36 + cb + 4]);
                al[mt][3] = __float_as_uint(Al[(r+8)*36 + cb + 4]);
            }
            #pragma unroll
            for (int nt=0; nt<4; nt++){
                int r = wn*32 + nt*8 + (lane>>2);
                bh[nt][0] = __float_as_uint(Bh[r*36 + cb]);
                bh[nt][1] = __float_as_uint(Bh[r*36 + cb + 4]);
                bl[nt][0] = __float_as_uint(Bl[r*36 + cb]);
                bl[nt][1] = __float_as_uint(Bl[r*36 + cb + 4]);
            }
            #pragma unroll
            for (int mt=0; mt<4; mt++)
                #pragma unroll
                for (int nt=0; nt<4; nt++){
                    MMA_TF32(c[mt][nt][0],c[mt][nt][1],c[mt][nt][2],c[mt][nt][3],
                             ah[mt][0],ah[mt][1],ah[mt][2],ah[mt][3], bh[nt][0],bh[nt][1]);
                    MMA_TF32(c[mt][nt][0],c[mt][nt][1],c[mt][nt][2],c[mt][nt][3],
                             ah[mt][0],ah[mt][1],ah[mt][2],ah[mt][3], bl[nt][0],bl[nt][1]);
                    MMA_TF32(c[mt][nt][0],c[mt][nt][1],c[mt][nt][2],c[mt][nt][3],
                             al[mt][0],al[mt][1],al[mt][2],al[mt][3], bh[nt][0],bh[nt][1]);
                }
        }
        __syncthreads();
    }

    #pragma unroll
    for (int mt=0; mt<4; mt++){
        int r = row0 + wm*64 + mt*16 + (lane>>2);
        #pragma unroll
        for (int nt=0; nt<4; nt++){
            int col = n0 + wn*32 + nt*8 + 2*(lane & 3);
            float b0v = bias[col], b1v = bias[col+1];
            float v0 = c[mt][nt][0] + b0v, v1 = c[mt][nt][1] + b1v;
            float v2 = c[mt][nt][2] + b0v, v3 = c[mt][nt][3] + b1v;
            if (RELU){ v0=fmaxf(v0,0.f); v1=fmaxf(v1,0.f); v2=fmaxf(v2,0.f); v3=fmaxf(v3,0.f); }
            *(float2*)&C[(size_t)r*N + col]     = make_float2(v0, v1);
            *(float2*)&C[(size_t)(r+8)*N + col] = make_float2(v2, v3);
        }
    }
}

// ---------- fused aggregate (R3, proven) -------------------------------------
template<bool HAS_TMP>
__global__ __launch_bounds__(256) void agg_k(
    const float* __restrict__ edge_x, const float* __restrict__ We,
    const float* __restrict__ be,     const float* __restrict__ tmp,
    const int* __restrict__ src,
    const float* __restrict__ hn_in,  float* __restrict__ hn_out)
{
    __shared__ float WeS[FE*HH];
    __shared__ float exs[NPB*DEG*FE];
    __shared__ int   srcS[NPB*DEG];
    const int tid = threadIdx.x;
    const int node0 = blockIdx.x * NPB;

    #pragma unroll
    for (int i = tid; i < FE*HH; i += 256) WeS[i] = We[i];
    for (int i = tid; i < NPB*DEG*FE; i += 256) exs[i] = edge_x[(size_t)node0*DEG*FE + i];
    if (tid < NPB*DEG) srcS[tid] = src[node0*DEG + tid];
    __syncthreads();

    const int j = tid;
    const float bej = be[j];
    #pragma unroll
    for (int nl = 0; nl < NPB; nl++){
        float tv[DEG];
        if (HAS_TMP){
            #pragma unroll
            for (int d=0; d<DEG; d++)
                tv[d] = tmp[(size_t)srcS[nl*DEG+d]*HH + j];
        }
        float s = 0.f, m = -INFINITY;
        #pragma unroll
        for (int d=0; d<DEG; d++){
            float v = bej;
            #pragma unroll
            for (int k=0; k<FE; k++)
                v = fmaf(exs[nl*DEG*FE + d*FE + k], WeS[k*HH + j], v);
            v = fmaxf(v, 0.f);
            if (HAS_TMP) v = fmaxf(v + tv[d], 0.f);
            s += v; m = fmaxf(m, v);
        }
        size_t r = (size_t)(node0+nl)*HH + j;
        hn_out[r] = hn_in[r] + s*m;
    }
}

__global__ __launch_bounds__(256) void cat_k(
    const float* __restrict__ edge_x, const float* __restrict__ We,
    const float* __restrict__ be,     const float* __restrict__ tmp,
    const int* __restrict__ src,
    const float* __restrict__ hn,     const float* __restrict__ in_,
    float* __restrict__ cat)
{
    __shared__ float WeS[FE*HH];
    __shared__ float exs[NPB*DEG*FE];
    __shared__ int   srcS[NPB*DEG];
    const int tid = threadIdx.x;
    const int node0 = blockIdx.x * NPB;

    #pragma unroll
    for (int i = tid; i < FE*HH; i += 256) WeS[i] = We[i];
    for (int i = tid; i < NPB*DEG*FE; i += 256) exs[i] = edge_x[(size_t)node0*DEG*FE + i];
    if (tid < NPB*DEG) srcS[tid] = src[node0*DEG + tid];
    __syncthreads();

    const int j = tid;
    const float bej = be[j];
    #pragma unroll
    for (int nl = 0; nl < NPB; nl++){
        float tv[DEG];
        #pragma unroll
        for (int d=0; d<DEG; d++)
            tv[d] = tmp[(size_t)srcS[nl*DEG+d]*HH + j];
        float s = 0.f, m = -INFINITY;
        #pragma unroll
        for (int d=0; d<DEG; d++){
            float v = bej;
            #pragma unroll
            for (int k=0; k<FE; k++)
                v = fmaf(exs[nl*DEG*FE + d*FE + k], WeS[k*HH + j], v);
            v = fmaxf(v, 0.f);
            v = fmaxf(v + tv[d], 0.f);
            s += v; m = fmaxf(m, v);
        }
        int node = node0 + nl;
        size_t r = (size_t)node*3*HH;
        cat[r + j]        = s*m;
        cat[r + HH + j]   = hn[(size_t)node*HH + j];
        cat[r + 2*HH + j] = in_[(size_t)node*HH + j];
    }
}

__global__ void msg_k(const float* __restrict__ hnl, const float* __restrict__ gbias,
                      float* __restrict__ msg)
{
    int i = blockIdx.x, j = threadIdx.x;
    msg[(size_t)i*HH + j] = fmaxf(hnl[(size_t)i*HH + j] + gbias[j], 0.f);
}

__global__ void init_h0_k(const float* __restrict__ hnl,
                          float* __restrict__ hf, float* __restrict__ hb,
                          float* __restrict__ accf, float* __restrict__ accb)
{
    int b = blockIdx.x, j = threadIdx.x;
    float m = -INFINITY;
    #pragma unroll 8
    for (int t=0; t<NPG; t++)
        m = fmaxf(m, hnl[((size_t)b*NPG + t)*HH + j]);
    hf[b*HH+j] = m; hb[b*HH+j] = m;
    accf[b*HH+j] = 0.f; accb[b*HH+j] = 0.f;
}

// ---------- fused GRU step (R3, proven) --------------------------------------
__global__ __launch_bounds__(256) void gru_step_k(
    const float* __restrict__ xgf, const float* __restrict__ xgb,
    const float* __restrict__ Whf, const float* __restrict__ Whb,
    const float* __restrict__ bhf, const float* __restrict__ bhb,
    const float* __restrict__ hf_in, const float* __restrict__ hb_in,
    float* __restrict__ hf_out, float* __restrict__ hb_out,
    float* __restrict__ accf, float* __restrict__ accb, int step)
{
    const int dir = blockIdx.z;
    const float* xg  = dir ? xgb : xgf;
    const float* Wh  = dir ? Whb : Whf;
    const float* bh  = dir ? bhb : bhf;
    const float* hin = dir ? hb_in : hf_in;
    float* hout = dir ? hb_out : hf_out;
    float* acc  = dir ? accb : accf;
    const int t = dir ? (NPG-1-step) : step;

    const int g0 = blockIdx.y*32, j0 = blockIdx.x*32;
    __shared__ float Hs[32][34];
    __shared__ float Ws[32][98];
    const int tid = threadIdx.x, tx = tid & 15, ty = tid >> 4;

    float a[2][6];
    #pragma unroll
    for (int i=0;i<2;i++)
        #pragma unroll
        for (int q=0;q<6;q++) a[i][q]=0.f;

    for (int k0 = 0; k0 < HH; k0 += 32){
        #pragma unroll
        for (int idx = tid; idx < 32*32; idx += 256){
            int kk = idx & 31, g = idx >> 5;
            Hs[kk][g] = hin[(size_t)(g0+g)*HH + k0 + kk];
        }
        #pragma unroll
        for (int idx = tid; idx < 32*96; idx += 256){
            int col = idx % 96, kk = idx / 96;
            int gate = col >> 5, jj = col & 31;
            Ws[kk][col] = Wh[(size_t)(k0+kk)*(3*HH) + gate*HH + j0 + jj];
        }
        __syncthreads();
        #pragma unroll
        for (int k=0;k<32;k++){
            float2 hv = *(const float2*)&Hs[k][ty*2];
            float2 b0 = *(const float2*)&Ws[k][ 0 + tx*2];
            float2 b1 = *(const float2*)&Ws[k][32 + tx*2];
            float2 b2 = *(const float2*)&Ws[k][64 + tx*2];
            a[0][0]=fmaf(hv.x,b0.x,a[0][0]); a[0][1]=fmaf(hv.x,b0.y,a[0][1]);
            a[0][2]=fmaf(hv.x,b1.x,a[0][2]); a[0][3]=fmaf(hv.x,b1.y,a[0][3]);
            a[0][4]=fmaf(hv.x,b2.x,a[0][4]); a[0][5]=fmaf(hv.x,b2.y,a[0][5]);
            a[1][0]=fmaf(hv.y,b0.x,a[1][0]); a[1][1]=fmaf(hv.y,b0.y,a[1][1]);
            a[1][2]=fmaf(hv.y,b1.x,a[1][2]); a[1][3]=fmaf(hv.y,b1.y,a[1][3]);
            a[1][4]=fmaf(hv.y,b2.x,a[1][4]); a[1][5]=fmaf(hv.y,b2.y,a[1][5]);
        }
        __syncthreads();
    }

    #pragma unroll
    for (int gm=0; gm<2; gm++){
        const int g = g0 + ty*2 + gm;
        const float* x = xg + ((size_t)g*NPG + t)*(3*HH);
        #pragma unroll
        for (int jj=0; jj<2; jj++){
            const int j = j0 + tx*2 + jj;
            float r = sigmoidf_(x[j]        + a[gm][0+jj] + bh[j]);
            float z = sigmoidf_(x[HH + j]   + a[gm][2+jj] + bh[HH + j]);
            float n = tanhf    (x[2*HH + j] + r*(a[gm][4+jj] + bh[2*HH + j]));
            float hold = hin[(size_t)g*HH + j];
            float hn = (1.0f - z)*n + z*hold;
            hout[(size_t)g*HH + j] = hn;
            acc[(size_t)g*HH + j] += hn;
        }
    }
}

__global__ void readout_k(const float* __restrict__ accf, const float* __restrict__ accb,
                          const float* __restrict__ W1, const float* __restrict__ b1,
                          const float* __restrict__ W2, const float* __restrict__ b2,
                          float* __restrict__ out)
{
    int b = blockIdx.x, j = threadIdx.x;
    __shared__ float gsh[2*HH];
    __shared__ float red[HH];
    gsh[j]      = accf[b*HH + j] * (1.0f/NPG);
    gsh[HH + j] = accb[b*HH + j] * (1.0f/NPG);
    __syncthreads();
    float y = b1[j];
    #pragma unroll 8
    for (int k=0; k<2*HH; k++)
        y = fmaf(gsh[k], W1[k*HH + j], y);
    y = fmaxf(y, 0.f);
    red[j] = y * W2[j];
    __syncthreads();
    for (int s=128; s>0; s>>=1){
        if (j < s) red[j] += red[j+s];
        __syncthreads();
    }
    if (j == 0) out[b] = red[0] + b2[0];
}

// =============================================================================
extern "C" void kernel_launch(void* const* d_in, const int* in_sizes, int n_in,
                              void* d_out, int out_size)
{
    const float* node_x = (const float*)d_in[0];
    const float* edge_x = (const float*)d_in[1];
    const int*   src    = (const int*)  d_in[2];
    const float* Wn  = (const float*)d_in[4];  const float* bn  = (const float*)d_in[5];
    const float* We  = (const float*)d_in[6];  const float* be  = (const float*)d_in[7];
    const float* Wm0 = (const float*)d_in[8];  const float* bm0 = (const float*)d_in[9];
    const float* Wm1 = (const float*)d_in[10]; const float* bm1 = (const float*)d_in[11];
    const float* Wlr = (const float*)d_in[12]; const float* blr = (const float*)d_in[13];
    const float* gbias = (const float*)d_in[14];
    const float* Wif = (const float*)d_in[15]; const float* Whf = (const float*)d_in[16];
    const float* bif = (const float*)d_in[17]; const float* bhf = (const float*)d_in[18];
    const float* Wib = (const float*)d_in[19]; const float* Whb = (const float*)d_in[20];
    const float* bib = (const float*)d_in[21]; const float* bhb = (const float*)d_in[22];
    const float* W1  = (const float*)d_in[23]; const float* b1  = (const float*)d_in[24];
    const float* W2  = (const float*)d_in[25]; const float* b2  = (const float*)d_in[26];
    float* out = (float*)d_out;

    float *p_in,*p_hn,*p_tmp,*p_cat,*p_hnl,*p_msg,*p_xgf,*p_xgb;
    float *p_hf0,*p_hf1,*p_hb0,*p_hb1,*p_accf,*p_accb;
    float *p_WnT,*p_Wm0T,*p_Wm1T,*p_WlrT,*p_WifT,*p_WibT;
    cudaGetSymbolAddress((void**)&p_in,  g_in);
    cudaGetSymbolAddress((void**)&p_hn,  g_hn);
    cudaGetSymbolAddress((void**)&p_tmp, g_tmp);
    cudaGetSymbolAddress((void**)&p_cat, g_cat);
    cudaGetSymbolAddress((void**)&p_hnl, g_hnl);
    cudaGetSymbolAddress((void**)&p_msg, g_msg);
    cudaGetSymbolAddress((void**)&p_xgf, g_xgf);
    cudaGetSymbolAddress((void**)&p_xgb, g_xgb);
    cudaGetSymbolAddress((void**)&p_hf0, g_hf0);
    cudaGetSymbolAddress((void**)&p_hf1, g_hf1);
    cudaGetSymbolAddress((void**)&p_hb0, g_hb0);
    cudaGetSymbolAddress((void**)&p_hb1, g_hb1);
    cudaGetSymbolAddress((void**)&p_accf, g_accf);
    cudaGetSymbolAddress((void**)&p_accb, g_accb);
    cudaGetSymbolAddress((void**)&p_WnT,  g_WnT);
    cudaGetSymbolAddress((void**)&p_Wm0T, g_Wm0T);
    cudaGetSymbolAddress((void**)&p_Wm1T, g_Wm1T);
    cudaGetSymbolAddress((void**)&p_WlrT, g_WlrT);
    cudaGetSymbolAddress((void**)&p_WifT, g_WifT);
    cudaGetSymbolAddress((void**)&p_WibT, g_WibT);

    cudaFuncSetAttribute(mma_gemm<true>,  cudaFuncAttributeMaxDynamicSharedMemorySize, GE_SMEM);
    cudaFuncSetAttribute(mma_gemm<false>, cudaFuncAttributeMaxDynamicSharedMemorySize, GE_SMEM);

    // 0) weight transposes (N-major, K-padded)
    prep_w<<<(HH*160+255)/256,    256>>>(Wn,  p_WnT,  FN,   HH,   160);
    prep_w<<<(HH*HH+255)/256,     256>>>(Wm0, p_Wm0T, HH,   HH,   HH);
    prep_w<<<(HH*HH+255)/256,     256>>>(Wm1, p_Wm1T, HH,   HH,   HH);
    prep_w<<<(HH*3*HH+255)/256,   256>>>(Wlr, p_WlrT, 3*HH, HH,   3*HH);
    prep_w<<<(3*HH*HH+255)/256,   256>>>(Wif, p_WifT, HH,   3*HH, HH);
    prep_w<<<(3*HH*HH+255)/256,   256>>>(Wib, p_WibT, HH,   3*HH, HH);

    // 1) node embedding
    mma_gemm<true><<<dim3(2,128), 256, GE_SMEM>>>(NN, HH, FN, 160, node_x, p_WnT, bn, p_in);

    // 2) round 1
    agg_k<false><<<NN/NPB, 256>>>(edge_x, We, be, nullptr, src, p_in, p_hn);
    mma_gemm<false><<<dim3(2,128), 256, GE_SMEM>>>(NN, HH, HH, HH, p_hn, p_Wm0T, bm0, p_tmp);

    // 3) round 2
    agg_k<true><<<NN/NPB, 256>>>(edge_x, We, be, p_tmp, src, p_hn, p_hn);
    mma_gemm<false><<<dim3(2,128), 256, GE_SMEM>>>(NN, HH, HH, HH, p_hn, p_Wm1T, bm1, p_tmp);

    // 4) final aggregate + concat + Wlr
    cat_k<<<NN/NPB, 256>>>(edge_x, We, be, p_tmp, src, p_hn, p_in, p_cat);
    mma_gemm<false><<<dim3(2,128), 256, GE_SMEM>>>(NN, HH, 3*HH, 3*HH, p_cat, p_WlrT, blr, p_hnl);

    // 5) GRU setup
    msg_k<<<NN, HH>>>(p_hnl, gbias, p_msg);
    init_h0_k<<<BB, HH>>>(p_hnl, p_hf0, p_hb0, p_accf, p_accb);
    mma_gemm<false><<<dim3(6,128), 256, GE_SMEM>>>(NN, 3*HH, HH, HH, p_msg, p_WifT, bif, p_xgf);
    mma_gemm<false><<<dim3(6,128), 256, GE_SMEM>>>(NN, 3*HH, HH, HH, p_msg, p_WibT, bib, p_xgb);

    // 6) GRU scan: 64 fused steps, double-buffered h (R3, proven)
    for (int step = 0; step < NPG; step++){
        float* hf_in  = (step & 1) ? p_hf1 : p_hf0;
        float* hf_out = (step & 1) ? p_hf0 : p_hf1;
        float* hb_in  = (step & 1) ? p_hb1 : p_hb0;
        float* hb_out = (step & 1) ? p_hb0 : p_hb1;
        gru_step_k<<<dim3(8,8,2), 256>>>(p_xgf, p_xgb, Whf, Whb, bhf, bhb,
                                         hf_in, hb_in, hf_out, hb_out,
                                         p_accf, p_accb, step);
    }

    // 7) readout
    readout_k<<<BB, HH>>>(p_accf, p_accb, W1, b1, W2, b2, out);
}

// round 7
// speedup vs baseline: 1.2757x; 1.0879x over previous
#include <cuda_runtime.h>
#include <cuda_bf16.h>
#include <math.h>
#include <stdint.h>

#define NN   16384
#define BB   256
#define NPG  64
#define DEG  8
#define EE   (NN*DEG)
#define HH   256
#define FN   133
#define FE   14
#define NPB  4
#define GNB  128

// ---------------- scratch ----------------------------------------------------
__device__ float g_in  [NN*HH];
__device__ float g_hn  [NN*HH];
__device__ float g_tmp [NN*HH];
__device__ float g_cat [NN*3*HH];
__device__ float g_hnl [NN*HH];
__device__ float g_msg [NN*HH];
__device__ float g_xgf [NN*3*HH];
__device__ float g_xgb [NN*3*HH];
__device__ float g_hf0 [BB*HH];
__device__ float g_hf1 [BB*HH];
__device__ float g_hb0 [BB*HH];
__device__ float g_hb1 [BB*HH];
__device__ float g_accf[BB*HH];
__device__ float g_accb[BB*HH];
__device__ unsigned g_bar;
// transposed (N-major, K-padded) weights
__device__ float g_WnT [HH*160];
__device__ float g_Wm0T[HH*HH];
__device__ float g_Wm1T[HH*HH];
__device__ float g_WlrT[HH*3*HH];
__device__ float g_WifT[3*HH*HH];
__device__ float g_WibT[3*HH*HH];

__device__ __forceinline__ float sigmoidf_(float x){ return 1.0f/(1.0f+expf(-x)); }

// hi = round-to-nearest tf32(a); lo = a - hi (exact)
__device__ __forceinline__ void split_tf32(float a, float& hi, float& lo){
    uint32_t u;
    asm("cvt.rna.tf32.f32 %0, %1;" : "=r"(u) : "f"(a));
    hi = __uint_as_float(u);
    lo = a - hi;
}

#define MMA_TF32(c0,c1,c2,c3,a0,a1,a2,a3,b0,b1) \
  asm volatile("mma.sync.aligned.m16n8k8.row.col.f32.tf32.tf32.f32 " \
    "{%0,%1,%2,%3}, {%4,%5,%6,%7}, {%8,%9}, {%0,%1,%2,%3};" \
    : "+f"(c0),"+f"(c1),"+f"(c2),"+f"(c3) \
    : "r"(a0),"r"(a1),"r"(a2),"r"(a3),"r"(b0),"r"(b1))

// ---------------- weight transpose + K-pad prep ------------------------------
__global__ void prep_w(const float* __restrict__ W, float* __restrict__ Wt,
                       int K, int N, int Kpad)
{
    int idx = blockIdx.x*256 + threadIdx.x;
    if (idx >= N*Kpad) return;
    int n = idx / Kpad, k = idx - n*Kpad;
    Wt[idx] = (k < K) ? W[(size_t)k*N + n] : 0.f;
}

// ---------------- mma.sync tf32 GEMM (3xTF32 split) --------------------------
#define GE_SMEM (4*128*36*4)
template<bool RELU>
__global__ __launch_bounds__(256) void mma_gemm(
    int M, int N, int Ktrue, int Kpad,
    const float* __restrict__ A, const float* __restrict__ Wt,
    const float* __restrict__ bias, float* __restrict__ C)
{
    extern __shared__ float sm[];
    float* Ah = sm;
    float* Al = Ah + 128*36;
    float* Bh = Al + 128*36;
    float* Bl = Bh + 128*36;
    const int tid = threadIdx.x, lane = tid & 31, wid = tid >> 5;
    const int wm = wid >> 2, wn = wid & 3;
    const int row0 = blockIdx.y*128, n0 = blockIdx.x*128;

    float c[4][4][4];
    #pragma unroll
    for (int mt=0; mt<4; mt++)
        #pragma unroll
        for (int nt=0; nt<4; nt++)
            #pragma unroll
            for (int q=0; q<4; q++) c[mt][nt][q] = 0.f;

    for (int k0 = 0; k0 < Kpad; k0 += 32){
        if ((Ktrue & 3) == 0){
            #pragma unroll
            for (int it=0; it<4; it++){
                int idx = it*256 + tid;
                int r = idx >> 3, cc = (idx & 7)*4;
                int gk = k0 + cc;
                float4 v = (gk < Ktrue) ? *(const float4*)&A[(size_t)(row0+r)*Ktrue + gk]
                                        : make_float4(0.f,0.f,0.f,0.f);
                float4 h4, l4;
                split_tf32(v.x,h4.x,l4.x); split_tf32(v.y,h4.y,l4.y);
                split_tf32(v.z,h4.z,l4.z); split_tf32(v.w,h4.w,l4.w);
                *(float4*)&Ah[r*36 + cc] = h4;
                *(float4*)&Al[r*36 + cc] = l4;
            }
        } else {
            #pragma unroll
            for (int it=0; it<16; it++){
                int idx = it*256 + tid;
                int r = idx >> 5, cc = idx & 31;
                int gk = k0 + cc;
                float v = (gk < Ktrue) ? A[(size_t)(row0+r)*Ktrue + gk] : 0.f;
                float h, l; split_tf32(v, h, l);
                Ah[r*36 + cc] = h; Al[r*36 + cc] = l;
            }
        }
        #pragma unroll
        for (int it=0; it<4; it++){
            int idx = it*256 + tid;
            int r = idx >> 3, cc = (idx & 7)*4;
            float4 v = *(const float4*)&Wt[(size_t)(n0+r)*Kpad + k0 + cc];
            float4 h4, l4;
            split_tf32(v.x,h4.x,l4.x); split_tf32(v.y,h4.y,l4.y);
            split_tf32(v.z,h4.z,l4.z); split_tf32(v.w,h4.w,l4.w);
            *(float4*)&Bh[r*36 + cc] = h4;
            *(float4*)&Bl[r*36 + cc] = l4;
        }
        __syncthreads();

        #pragma unroll
        for (int kk=0; kk<32; kk+=8){
            uint32_t ah[4][4], al[4][4], bh[4][2], bl[4][2];
            const int cb = kk + (lane & 3);
            #pragma unroll
            for (int mt=0; mt<4; mt++){
                int r = wm*64 + mt*16 + (lane>>2);
                ah[mt][0] = __float_as_uint(Ah[r*36 + cb]);
                ah[mt][1] = __float_as_uint(Ah[(r+8)*36 + cb]);
                ah[mt][2] = __float_as_uint(Ah[r*36 + cb + 4]);
                ah[mt][3] = __float_as_uint(Ah[(r+8)*36 + cb + 4]);
                al[mt][0] = __float_as_uint(Al[r*36 + cb]);
                al[mt][1] = __float_as_uint(Al[(r+8)*36 + cb]);
                al[mt][2] = __float_as_uint(Al[r*36 + cb + 4]);
                al[mt][3] = __float_as_uint(Al[(r+8)*36 + cb + 4]);
            }
            #pragma unroll
            for (int nt=0; nt<4; nt++){
                int r = wn*32 + nt*8 + (lane>>2);
                bh[nt][0] = __float_as_uint(Bh[r*36 + cb]);
                bh[nt][1] = __float_as_uint(Bh[r*36 + cb + 4]);
                bl[nt][0] = __float_as_uint(Bl[r*36 + cb]);
                bl[nt][1] = __float_as_uint(Bl[r*36 + cb + 4]);
            }
            #pragma unroll
            for (int mt=0; mt<4; mt++)
                #pragma unroll
                for (int nt=0; nt<4; nt++){
                    MMA_TF32(c[mt][nt][0],c[mt][nt][1],c[mt][nt][2],c[mt][nt][3],
                             ah[mt][0],ah[mt][1],ah[mt][2],ah[mt][3], bh[nt][0],bh[nt][1]);
                    MMA_TF32(c[mt][nt][0],c[mt][nt][1],c[mt][nt][2],c[mt][nt][3],
                             ah[mt][0],ah[mt][1],ah[mt][2],ah[mt][3], bl[nt][0],bl[nt][1]);
                    MMA_TF32(c[mt][nt][0],c[mt][nt][1],c[mt][nt][2],c[mt][nt][3],
                             al[mt][0],al[mt][1],al[mt][2],al[mt][3], bh[nt][0],bh[nt][1]);
                }
        }
        __syncthreads();
    }

    #pragma unroll
    for (int mt=0; mt<4; mt++){
        int r = row0 + wm*64 + mt*16 + (lane>>2);
        #pragma unroll
        for (int nt=0; nt<4; nt++){
            int col = n0 + wn*32 + nt*8 + 2*(lane & 3);
            float b0v = bias[col], b1v = bias[col+1];
            float v0 = c[mt][nt][0] + b0v, v1 = c[mt][nt][1] + b1v;
            float v2 = c[mt][nt][2] + b0v, v3 = c[mt][nt][3] + b1v;
            if (RELU){ v0=fmaxf(v0,0.f); v1=fmaxf(v1,0.f); v2=fmaxf(v2,0.f); v3=fmaxf(v3,0.f); }
            *(float2*)&C[(size_t)r*N + col]     = make_float2(v0, v1);
            *(float2*)&C[(size_t)(r+8)*N + col] = make_float2(v2, v3);
        }
    }
}

// ---------- fused aggregate (proven) -----------------------------------------
template<bool HAS_TMP>
__global__ __launch_bounds__(256) void agg_k(
    const float* __restrict__ edge_x, const float* __restrict__ We,
    const float* __restrict__ be,     const float* __restrict__ tmp,
    const int* __restrict__ src,
    const float* __restrict__ hn_in,  float* __restrict__ hn_out)
{
    __shared__ float WeS[FE*HH];
    __shared__ float exs[NPB*DEG*FE];
    __shared__ int   srcS[NPB*DEG];
    const int tid = threadIdx.x;
    const int node0 = blockIdx.x * NPB;

    #pragma unroll
    for (int i = tid; i < FE*HH; i += 256) WeS[i] = We[i];
    for (int i = tid; i < NPB*DEG*FE; i += 256) exs[i] = edge_x[(size_t)node0*DEG*FE + i];
    if (tid < NPB*DEG) srcS[tid] = src[node0*DEG + tid];
    __syncthreads();

    const int j = tid;
    const float bej = be[j];
    #pragma unroll
    for (int nl = 0; nl < NPB; nl++){
        float tv[DEG];
        if (HAS_TMP){
            #pragma unroll
            for (int d=0; d<DEG; d++)
                tv[d] = tmp[(size_t)srcS[nl*DEG+d]*HH + j];
        }
        float s = 0.f, m = -INFINITY;
        #pragma unroll
        for (int d=0; d<DEG; d++){
            float v = bej;
            #pragma unroll
            for (int k=0; k<FE; k++)
                v = fmaf(exs[nl*DEG*FE + d*FE + k], WeS[k*HH + j], v);
            v = fmaxf(v, 0.f);
            if (HAS_TMP) v = fmaxf(v + tv[d], 0.f);
            s += v; m = fmaxf(m, v);
        }
        size_t r = (size_t)(node0+nl)*HH + j;
        hn_out[r] = hn_in[r] + s*m;
    }
}

__global__ __launch_bounds__(256) void cat_k(
    const float* __restrict__ edge_x, const float* __restrict__ We,
    const float* __restrict__ be,     const float* __restrict__ tmp,
    const int* __restrict__ src,
    const float* __restrict__ hn,     const float* __restrict__ in_,
    float* __restrict__ cat)
{
    __shared__ float WeS[FE*HH];
    __shared__ float exs[NPB*DEG*FE];
    __shared__ int   srcS[NPB*DEG];
    const int tid = threadIdx.x;
    const int node0 = blockIdx.x * NPB;

    #pragma unroll
    for (int i = tid; i < FE*HH; i += 256) WeS[i] = We[i];
    for (int i = tid; i < NPB*DEG*FE; i += 256) exs[i] = edge_x[(size_t)node0*DEG*FE + i];
    if (tid < NPB*DEG) srcS[tid] = src[node0*DEG + tid];
    __syncthreads();

    const int j = tid;
    const float bej = be[j];
    #pragma unroll
    for (int nl = 0; nl < NPB; nl++){
        float tv[DEG];
        #pragma unroll
        for (int d=0; d<DEG; d++)
            tv[d] = tmp[(size_t)srcS[nl*DEG+d]*HH + j];
        float s = 0.f, m = -INFINITY;
        #pragma unroll
        for (int d=0; d<DEG; d++){
            float v = bej;
            #pragma unroll
            for (int k=0; k<FE; k++)
                v = fmaf(exs[nl*DEG*FE + d*FE + k], WeS[k*HH + j], v);
            v = fmaxf(v, 0.f);
            v = fmaxf(v + tv[d], 0.f);
            s += v; m = fmaxf(m, v);
        }
        int node = node0 + nl;
        size_t r = (size_t)node*3*HH;
        cat[r + j]        = s*m;
        cat[r + HH + j]   = hn[(size_t)node*HH + j];
        cat[r + 2*HH + j] = in_[(size_t)node*HH + j];
    }
}

__global__ void msg_k(const float* __restrict__ hnl, const float* __restrict__ gbias,
                      float* __restrict__ msg)
{
    int i = blockIdx.x, j = threadIdx.x;
    msg[(size_t)i*HH + j] = fmaxf(hnl[(size_t)i*HH + j] + gbias[j], 0.f);
}

__global__ void init_h0_k(const float* __restrict__ hnl,
                          float* __restrict__ hf, float* __restrict__ hb,
                          float* __restrict__ accf, float* __restrict__ accb)
{
    int b = blockIdx.x, j = threadIdx.x;
    float m = -INFINITY;
    #pragma unroll 8
    for (int t=0; t<NPG; t++)
        m = fmaxf(m, hnl[((size_t)b*NPG + t)*HH + j]);
    hf[b*HH+j] = m; hb[b*HH+j] = m;
    accf[b*HH+j] = 0.f; accb[b*HH+j] = 0.f;
}

__global__ void bar_reset_k(){ g_bar = 0u; }

// ---------- persistent GRU: proven gru_step_k tiling + resident Ws + barrier --
// 128 blocks: bid = jt(8) | gt(8)<<3 | dir<<6. Dynamic smem: Ws[256][98].
#define GRU_SMEM (256*98*4)
__global__ __launch_bounds__(256) void gru_persist(
    const float* __restrict__ xgf, const float* __restrict__ xgb,
    const float* __restrict__ Whf, const float* __restrict__ Whb,
    const float* __restrict__ bhf, const float* __restrict__ bhb,
    float* __restrict__ hf0, float* __restrict__ hf1,
    float* __restrict__ hb0, float* __restrict__ hb1,
    float* __restrict__ accf, float* __restrict__ accb)
{
    extern __shared__ float ws[];          // [256][98] (stride 98, cols 0..95)
    __shared__ float Hs[32][34];
    __shared__ float bhs[96];

    const int bid = blockIdx.x;
    const int jt = bid & 7, gt = (bid >> 3) & 7, dir = bid >> 6;
    const int j0 = jt*32, g0 = gt*32;
    const float* xg = dir ? xgb : xgf;
    const float* Wh = dir ? Whb : Whf;
    const float* bh = dir ? bhb : bhf;
    float* b0buf = dir ? hb0 : hf0;
    float* b1buf = dir ? hb1 : hf1;
    float* accg  = dir ? accb : accf;

    const int tid = threadIdx.x, tx = tid & 15, ty = tid >> 4;

    // load Ws once (resident across all 64 steps)
    for (int idx = tid; idx < 256*96; idx += 256){
        int col = idx % 96, k = idx / 96;
        int gate = col >> 5, jj = col & 31;
        ws[k*98 + col] = Wh[(size_t)k*(3*HH) + gate*HH + j0 + jj];
    }
    if (tid < 96){
        int gate = tid >> 5, jj = tid & 31;
        bhs[tid] = bh[gate*HH + j0 + jj];
    }

    // per-thread h state (2 graphs x 2 cols) + mean accumulator
    float hold[2][2], acc[2][2];
    #pragma unroll
    for (int gm=0; gm<2; gm++)
        #pragma unroll
        for (int jj=0; jj<2; jj++){
            hold[gm][jj] = b0buf[(size_t)(g0 + ty*2 + gm)*HH + j0 + tx*2 + jj];
            acc[gm][jj] = 0.f;
        }
    __syncthreads();

    for (int s = 0; s < NPG; s++){
        const float* hin = (s & 1) ? b1buf : b0buf;
        float*       hout= (s & 1) ? b0buf : b1buf;
        const int t = dir ? (NPG-1-s) : s;

        float a[2][6];
        #pragma unroll
        for (int i=0;i<2;i++)
            #pragma unroll
            for (int q=0;q<6;q++) a[i][q]=0.f;

        for (int k0 = 0; k0 < HH; k0 += 32){
            #pragma unroll
            for (int idx = tid; idx < 32*32; idx += 256){
                int kk = idx & 31, g = idx >> 5;
                Hs[kk][g] = hin[(size_t)(g0+g)*HH + k0 + kk];
            }
            __syncthreads();
            #pragma unroll
            for (int k=0;k<32;k++){
                const float* wrow = &ws[(k0+k)*98];
                float2 hv = *(const float2*)&Hs[k][ty*2];
                float2 w0 = *(const float2*)&wrow[ 0 + tx*2];
                float2 w1 = *(const float2*)&wrow[32 + tx*2];
                float2 w2 = *(const float2*)&wrow[64 + tx*2];
                a[0][0]=fmaf(hv.x,w0.x,a[0][0]); a[0][1]=fmaf(hv.x,w0.y,a[0][1]);
                a[0][2]=fmaf(hv.x,w1.x,a[0][2]); a[0][3]=fmaf(hv.x,w1.y,a[0][3]);
                a[0][4]=fmaf(hv.x,w2.x,a[0][4]); a[0][5]=fmaf(hv.x,w2.y,a[0][5]);
                a[1][0]=fmaf(hv.y,w0.x,a[1][0]); a[1][1]=fmaf(hv.y,w0.y,a[1][1]);
                a[1][2]=fmaf(hv.y,w1.x,a[1][2]); a[1][3]=fmaf(hv.y,w1.y,a[1][3]);
                a[1][4]=fmaf(hv.y,w2.x,a[1][4]); a[1][5]=fmaf(hv.y,w2.y,a[1][5]);
            }
            __syncthreads();
        }

        #pragma unroll
        for (int gm=0; gm<2; gm++){
            const int g = g0 + ty*2 + gm;
            const float* x = xg + ((size_t)g*NPG + t)*(3*HH);
            #pragma unroll
            for (int jj=0; jj<2; jj++){
                const int j = j0 + tx*2 + jj;
                const int jc = tx*2 + jj;
                float r = sigmoidf_(x[j]        + a[gm][0+jj] + bhs[jc]);
                float z = sigmoidf_(x[HH + j]   + a[gm][2+jj] + bhs[32+jc]);
                float n = tanhf    (x[2*HH + j] + r*(a[gm][4+jj] + bhs[64+jc]));
                float hv = (1.0f - z)*n + z*hold[gm][jj];
                hold[gm][jj] = hv;
                acc[gm][jj] += hv;
                hout[(size_t)g*HH + j] = hv;
            }
        }

        // grid-wide barrier (release arrive + acquire spin)
        if (s < NPG-1){
            __threadfence();
            __syncthreads();
            if (tid == 0){
                unsigned target = (unsigned)(s+1) * GNB;
                asm volatile("red.release.gpu.add.u32 [%0], %1;"
                             :: "l"(&g_bar), "r"(1u) : "memory");
                unsigned v;
                do {
                    asm volatile("ld.acquire.gpu.u32 %0, [%1];"
                                 : "=r"(v) : "l"(&g_bar) : "memory");
                } while (v < target);
            }
            __syncthreads();
        }
    }

    #pragma unroll
    for (int gm=0; gm<2; gm++)
        #pragma unroll
        for (int jj=0; jj<2; jj++)
            accg[(size_t)(g0 + ty*2 + gm)*HH + j0 + tx*2 + jj] = acc[gm][jj];
}

__global__ void readout_k(const float* __restrict__ accf, const float* __restrict__ accb,
                          const float* __restrict__ W1, const float* __restrict__ b1,
                          const float* __restrict__ W2, const float* __restrict__ b2,
                          float* __restrict__ out)
{
    int b = blockIdx.x, j = threadIdx.x;
    __shared__ float gsh[2*HH];
    __shared__ float red[HH];
    gsh[j]      = accf[b*HH + j] * (1.0f/NPG);
    gsh[HH + j] = accb[b*HH + j] * (1.0f/NPG);
    __syncthreads();
    float y = b1[j];
    #pragma unroll 8
    for (int k=0; k<2*HH; k++)
        y = fmaf(gsh[k], W1[k*HH + j], y);
    y = fmaxf(y, 0.f);
    red[j] = y * W2[j];
    __syncthreads();
    for (int s=128; s>0; s>>=1){
        if (j < s) red[j] += red[j+s];
        __syncthreads();
    }
    if (j == 0) out[b] = red[0] + b2[0];
}

// =============================================================================
extern "C" void kernel_launch(void* const* d_in, const int* in_sizes, int n_in,
                              void* d_out, int out_size)
{
    const float* node_x = (const float*)d_in[0];
    const float* edge_x = (const float*)d_in[1];
    const int*   src    = (const int*)  d_in[2];
    const float* Wn  = (const float*)d_in[4];  const float* bn  = (const float*)d_in[5];
    const float* We  = (const float*)d_in[6];  const float* be  = (const float*)d_in[7];
    const float* Wm0 = (const float*)d_in[8];  const float* bm0 = (const float*)d_in[9];
    const float* Wm1 = (const float*)d_in[10]; const float* bm1 = (const float*)d_in[11];
    const float* Wlr = (const float*)d_in[12]; const float* blr = (const float*)d_in[13];
    const float* gbias = (const float*)d_in[14];
    const float* Wif = (const float*)d_in[15]; const float* Whf = (const float*)d_in[16];
    const float* bif = (const float*)d_in[17]; const float* bhf = (const float*)d_in[18];
    const float* Wib = (const float*)d_in[19]; const float* Whb = (const float*)d_in[20];
    const float* bib = (const float*)d_in[21]; const float* bhb = (const float*)d_in[22];
    const float* W1  = (const float*)d_in[23]; const float* b1  = (const float*)d_in[24];
    const float* W2  = (const float*)d_in[25]; const float* b2  = (const float*)d_in[26];
    float* out = (float*)d_out;

    float *p_in,*p_hn,*p_tmp,*p_cat,*p_hnl,*p_msg,*p_xgf,*p_xgb;
    float *p_hf0,*p_hf1,*p_hb0,*p_hb1,*p_accf,*p_accb;
    float *p_WnT,*p_Wm0T,*p_Wm1T,*p_WlrT,*p_WifT,*p_WibT;
    cudaGetSymbolAddress((void**)&p_in,  g_in);
    cudaGetSymbolAddress((void**)&p_hn,  g_hn);
    cudaGetSymbolAddress((void**)&p_tmp, g_tmp);
    cudaGetSymbolAddress((void**)&p_cat, g_cat);
    cudaGetSymbolAddress((void**)&p_hnl, g_hnl);
    cudaGetSymbolAddress((void**)&p_msg, g_msg);
    cudaGetSymbolAddress((void**)&p_xgf, g_xgf);
    cudaGetSymbolAddress((void**)&p_xgb, g_xgb);
    cudaGetSymbolAddress((void**)&p_hf0, g_hf0);
    cudaGetSymbolAddress((void**)&p_hf1, g_hf1);
    cudaGetSymbolAddress((void**)&p_hb0, g_hb0);
    cudaGetSymbolAddress((void**)&p_hb1, g_hb1);
    cudaGetSymbolAddress((void**)&p_accf, g_accf);
    cudaGetSymbolAddress((void**)&p_accb, g_accb);
    cudaGetSymbolAddress((void**)&p_WnT,  g_WnT);
    cudaGetSymbolAddress((void**)&p_Wm0T, g_Wm0T);
    cudaGetSymbolAddress((void**)&p_Wm1T, g_Wm1T);
    cudaGetSymbolAddress((void**)&p_WlrT, g_WlrT);
    cudaGetSymbolAddress((void**)&p_WifT, g_WifT);
    cudaGetSymbolAddress((void**)&p_WibT, g_WibT);

    cudaFuncSetAttribute(mma_gemm<true>,  cudaFuncAttributeMaxDynamicSharedMemorySize, GE_SMEM);
    cudaFuncSetAttribute(mma_gemm<false>, cudaFuncAttributeMaxDynamicSharedMemorySize, GE_SMEM);
    cudaFuncSetAttribute(gru_persist,     cudaFuncAttributeMaxDynamicSharedMemorySize, GRU_SMEM);

    // 0) weight transposes (N-major, K-padded)
    prep_w<<<(HH*160+255)/256,    256>>>(Wn,  p_WnT,  FN,   HH,   160);
    prep_w<<<(HH*HH+255)/256,     256>>>(Wm0, p_Wm0T, HH,   HH,   HH);
    prep_w<<<(HH*HH+255)/256,     256>>>(Wm1, p_Wm1T, HH,   HH,   HH);
    prep_w<<<(HH*3*HH+255)/256,   256>>>(Wlr, p_WlrT, 3*HH, HH,   3*HH);
    prep_w<<<(3*HH*HH+255)/256,   256>>>(Wif, p_WifT, HH,   3*HH, HH);
    prep_w<<<(3*HH*HH+255)/256,   256>>>(Wib, p_WibT, HH,   3*HH, HH);

    // 1) node embedding
    mma_gemm<true><<<dim3(2,128), 256, GE_SMEM>>>(NN, HH, FN, 160, node_x, p_WnT, bn, p_in);

    // 2) round 1
    agg_k<false><<<NN/NPB, 256>>>(edge_x, We, be, nullptr, src, p_in, p_hn);
    mma_gemm<false><<<dim3(2,128), 256, GE_SMEM>>>(NN, HH, HH, HH, p_hn, p_Wm0T, bm0, p_tmp);

    // 3) round 2
    agg_k<true><<<NN/NPB, 256>>>(edge_x, We, be, p_tmp, src, p_hn, p_hn);
    mma_gemm<false><<<dim3(2,128), 256, GE_SMEM>>>(NN, HH, HH, HH, p_hn, p_Wm1T, bm1, p_tmp);

    // 4) final aggregate + concat + Wlr
    cat_k<<<NN/NPB, 256>>>(edge_x, We, be, p_tmp, src, p_hn, p_in, p_cat);
    mma_gemm<false><<<dim3(2,128), 256, GE_SMEM>>>(NN, HH, 3*HH, 3*HH, p_cat, p_WlrT, blr, p_hnl);

    // 5) GRU setup
    msg_k<<<NN, HH>>>(p_hnl, gbias, p_msg);
    init_h0_k<<<BB, HH>>>(p_hnl, p_hf0, p_hb0, p_accf, p_accb);
    mma_gemm<false><<<dim3(6,128), 256, GE_SMEM>>>(NN, 3*HH, HH, HH, p_msg, p_WifT, bif, p_xgf);
    mma_gemm<false><<<dim3(6,128), 256, GE_SMEM>>>(NN, 3*HH, HH, HH, p_msg, p_WibT, bib, p_xgb);

    // 6) persistent GRU (64 steps, in-kernel grid barrier)
    bar_reset_k<<<1,1>>>();
    gru_persist<<<GNB, 256, GRU_SMEM>>>(p_xgf, p_xgb, Whf, Whb, bhf, bhb,
                                        p_hf0, p_hf1, p_hb0, p_hb1, p_accf, p_accb);

    // 7) readout
    readout_k<<<BB, HH>>>(p_accf, p_accb, W1, b1, W2, b2, out);
}